// round 16
// baseline (speedup 1.0000x reference)
#include <cuda_runtime.h>
#include <cstdint>

// Scatter-add message passing: out[dst] += x[src]
// x: [N, 64] fp32; edge_index: [2, E] int32.
//
// R16 = R14 with ONE change: no "memory" clobber on the RED asm.
// The clobber forced all loads to stay above all REDs program-wide; without
// it the SASS scheduler may interleave REDs with remaining gathers (each RED
// is still data-ordered after its own gather via operand dependence; REDs
// are no-return; out is never read in-kernel; kernel boundary flushes).
//
// Locked config (swept R2-R15): 16 lanes per 4-edge group, lane c owns
// float4 chunk c; int4 index loads; MLP=4 __ldg gathers; v4 REDs;
// __launch_bounds__(256,8); zero-kernel wrapper (memset/PDL equivalent).

__global__ void k_zero(float4* __restrict__ out, int n4) {
    int i = blockIdx.x * blockDim.x + threadIdx.x;
    if (i < n4) out[i] = make_float4(0.f, 0.f, 0.f, 0.f);
}

// volatile keeps the REDs emitted and mutually ordered; no memory clobber.
__device__ __forceinline__ void red_v4(float* out, int dst, int c, float4 v) {
    float4* op = (float4*)(out + (size_t)dst * 64) + c;
    asm volatile("red.global.add.v4.f32 [%0], {%1, %2, %3, %4};"
                 :: "l"(op), "f"(v.x), "f"(v.y), "f"(v.z), "f"(v.w));
}

__global__ void __launch_bounds__(256, 8)
mp_scatter4_kernel(const float* __restrict__ x,
                   const int* __restrict__ ei,
                   float* __restrict__ out,
                   int E, int G) {
    int tid = blockIdx.x * blockDim.x + threadIdx.x;
    int g = tid >> 4;           // group of 4 consecutive edges
    int c = tid & 15;           // float4 chunk within the 64-float row
    if (g >= G) return;

    int e0 = g << 2;

    if (e0 + 4 <= E) {          // fast path (always taken for E % 4 == 0)
        int4 d4 = __ldg((const int4*)(ei + e0));
        int4 s4 = __ldg((const int4*)(ei + E + e0));

        float4 v0 = __ldg((const float4*)(x + (size_t)s4.x * 64) + c);
        float4 v1 = __ldg((const float4*)(x + (size_t)s4.y * 64) + c);
        float4 v2 = __ldg((const float4*)(x + (size_t)s4.z * 64) + c);
        float4 v3 = __ldg((const float4*)(x + (size_t)s4.w * 64) + c);

        red_v4(out, d4.x, c, v0);
        red_v4(out, d4.y, c, v1);
        red_v4(out, d4.z, c, v2);
        red_v4(out, d4.w, c, v3);
    } else {                    // tail (dead for E = 800000; kept for safety)
        for (int e = e0; e < E; e++) {
            int dst = __ldg(ei + e);
            int src = __ldg(ei + E + e);
            float4 v = __ldg((const float4*)(x + (size_t)src * 64) + c);
            red_v4(out, dst, c, v);
        }
    }
}

extern "C" void kernel_launch(void* const* d_in, const int* in_sizes, int n_in,
                              void* d_out, int out_size) {
    const float* x = (const float*)d_in[0];
    const int* ei = (const int*)d_in[1];
    float* out = (float*)d_out;

    int E = in_sizes[1] / 2;            // edge_index is [2, E]
    int G = (E + 3) / 4;                // groups of 4 edges

    int n4 = out_size / 4;              // float4 count of out
    int tb = 256;
    k_zero<<<(n4 + tb - 1) / tb, tb>>>((float4*)out, n4);

    long long total = (long long)G * 16;
    int blocks = (int)((total + tb - 1) / tb);
    mp_scatter4_kernel<<<blocks, tb>>>(x, ei, out, E, G);
}

// round 17
// speedup vs baseline: 1.0050x; 1.0050x over previous
#include <cuda_runtime.h>
#include <cstdint>

// Scatter-add message passing: out[dst] += x[src]
// x: [N, 64] fp32; edge_index: [2, E] int32.
//
// FINAL (R17 = R14, best measured config; search converged):
//  - kernel floor 41.4us = LTS-traffic bound (205MB gather + 205MB atomic
//    RMW at the ~6KB/cyc L2 cap); wall floor ~45.0us (replay-fixed gap).
//  - Swept and settled: MLP{1,4,8,persistent}->4; cache{__ldg,.cg}->__ldg;
//    sort-based -> dead (2x); dtype -> hardcoded int32; wrapper
//    {zero-kernel,memset,PDL} -> equivalent; RED clobber -> neutral.
//
// Body: 16 lanes per group of 4 edges; lane c owns float4 chunk c of the
// 64-float row. int4 index loads -> 4 independent __ldg gathers -> 4
// fire-and-forget red.global.add.v4.f32. regs 26, full occupancy.

__global__ void k_zero(float4* __restrict__ out, int n4) {
    int i = blockIdx.x * blockDim.x + threadIdx.x;
    if (i < n4) out[i] = make_float4(0.f, 0.f, 0.f, 0.f);
}

__device__ __forceinline__ void red_v4(float* out, int dst, int c, float4 v) {
    float4* op = (float4*)(out + (size_t)dst * 64) + c;
    asm volatile("red.global.add.v4.f32 [%0], {%1, %2, %3, %4};"
                 :: "l"(op), "f"(v.x), "f"(v.y), "f"(v.z), "f"(v.w)
                 : "memory");
}

__global__ void __launch_bounds__(256, 8)
mp_scatter4_kernel(const float* __restrict__ x,
                   const int* __restrict__ ei,
                   float* __restrict__ out,
                   int E, int G) {
    int tid = blockIdx.x * blockDim.x + threadIdx.x;
    int g = tid >> 4;           // group of 4 consecutive edges
    int c = tid & 15;           // float4 chunk within the 64-float row
    if (g >= G) return;

    int e0 = g << 2;
    int n = min(4, E - e0);     // edges in this group (tail-safe)

    int dst[4], src[4];
    if (n == 4) {               // aligned: e0 % 4 == 0
        int4 d4 = __ldg((const int4*)(ei + e0));
        int4 s4 = __ldg((const int4*)(ei + E + e0));
        dst[0] = d4.x; dst[1] = d4.y; dst[2] = d4.z; dst[3] = d4.w;
        src[0] = s4.x; src[1] = s4.y; src[2] = s4.z; src[3] = s4.w;
    } else {
        #pragma unroll
        for (int k = 0; k < 4; k++) {
            int e = e0 + ((k < n) ? k : 0);
            dst[k] = __ldg(ei + e);
            src[k] = __ldg(ei + E + e);
        }
    }

    // All 4 gathers in flight before any RED (asm memory clobber would
    // otherwise serialize load->red pairs).
    float4 v[4];
    #pragma unroll
    for (int k = 0; k < 4; k++)
        v[k] = __ldg((const float4*)(x + (size_t)src[k] * 64) + c);

    // Fire-and-forget reductions.
    #pragma unroll
    for (int k = 0; k < 4; k++)
        if (k < n) red_v4(out, dst[k], c, v[k]);
}

extern "C" void kernel_launch(void* const* d_in, const int* in_sizes, int n_in,
                              void* d_out, int out_size) {
    const float* x = (const float*)d_in[0];
    const int* ei = (const int*)d_in[1];
    float* out = (float*)d_out;

    int E = in_sizes[1] / 2;            // edge_index is [2, E]
    int G = (E + 3) / 4;                // groups of 4 edges

    int n4 = out_size / 4;              // float4 count of out
    int tb = 256;
    k_zero<<<(n4 + tb - 1) / tb, tb>>>((float4*)out, n4);

    long long total = (long long)G * 16;
    int blocks = (int)((total + tb - 1) / tb);
    mp_scatter4_kernel<<<blocks, tb>>>(x, ei, out, E, G);
}